// round 1
// baseline (speedup 1.0000x reference)
#include <cuda_runtime.h>
#include <math.h>

#define BATCH 4
#define CHN   512
#define HW    4096
#define EPSF  1e-5f

// ---------------- scratch (device globals; no allocations allowed) ----------
__device__ float g_F[BATCH * CHN * HW];                 // 32 MB
__device__ float g_G[BATCH * CHN * HW];                 // 32 MB
__device__ float g_H[BATCH * CHN * HW];                 // 32 MB
__device__ float g_O[BATCH * CHN * HW];                 // 32 MB
__device__ float g_S[(size_t)BATCH * HW * HW];          // 256 MB
__device__ float g_mean[2 * BATCH * CHN];
__device__ float g_rstd[2 * BATCH * CHN];

// ---------------- per-(b,c) mean / rstd over 4096 spatial elems -------------
__global__ void __launch_bounds__(256)
stats_kernel(const float* __restrict__ content, const float* __restrict__ style)
{
    int bc  = blockIdx.x;                       // b*CHN + c
    int sel = blockIdx.y;                       // 0 = content, 1 = style
    const float* x = (sel == 0 ? content : style) + (size_t)bc * HW;

    float s1 = 0.f, s2 = 0.f;
    for (int i = threadIdx.x * 4; i < HW; i += 256 * 4) {
        float4 v = *(const float4*)&x[i];
        s1 += v.x + v.y + v.z + v.w;
        s2 += v.x * v.x + v.y * v.y + v.z * v.z + v.w * v.w;
    }
    __shared__ float sh1[8], sh2[8];
    for (int o = 16; o > 0; o >>= 1) {
        s1 += __shfl_xor_sync(0xffffffffu, s1, o);
        s2 += __shfl_xor_sync(0xffffffffu, s2, o);
    }
    int warp = threadIdx.x >> 5, lane = threadIdx.x & 31;
    if (lane == 0) { sh1[warp] = s1; sh2[warp] = s2; }
    __syncthreads();
    if (threadIdx.x < 32) {
        s1 = (lane < 8) ? sh1[lane] : 0.f;
        s2 = (lane < 8) ? sh2[lane] : 0.f;
        for (int o = 4; o > 0; o >>= 1) {
            s1 += __shfl_xor_sync(0xffffffffu, s1, o);
            s2 += __shfl_xor_sync(0xffffffffu, s2, o);
        }
        if (lane == 0) {
            float mean = s1 / (float)HW;
            float var  = (s2 - s1 * mean) / (float)(HW - 1);   // unbiased
            int idx = sel * BATCH * CHN + bc;
            g_mean[idx] = mean;
            g_rstd[idx] = rsqrtf(var + EPSF);
        }
    }
}

// ---------------- shared microkernel: 128x128 block, 8x8 per thread ---------
#define MICRO_KERNEL(As, Bs, acc, tx, ty)                                      \
    _Pragma("unroll")                                                          \
    for (int kk = 0; kk < 16; kk++) {                                          \
        float ar[8], br[8];                                                    \
        _Pragma("unroll")                                                      \
        for (int i = 0; i < 8; i++) ar[i] = As[kk][(ty) * 8 + i];              \
        _Pragma("unroll")                                                      \
        for (int j = 0; j < 8; j++) br[j] = Bs[kk][(tx) * 8 + j];              \
        _Pragma("unroll")                                                      \
        for (int i = 0; i < 8; i++)                                            \
            _Pragma("unroll")                                                  \
            for (int j = 0; j < 8; j++)                                        \
                acc[i][j] = fmaf(ar[i], br[j], acc[i][j]);                     \
    }

// ---------------- GEMM NN: C[b] = A(MxK) * B[b](KxN) + bias (+resid) --------
// Used for the three input convs (optionally normalizing B rows) and the
// output conv (adding the content residual).
template<bool NORMB, bool RESID>
__global__ void __launch_bounds__(256)
gemm_nn(const float* __restrict__ A, const float* __restrict__ Bg,
        const float* __restrict__ bias, const float* __restrict__ residg,
        int statOff, float* __restrict__ Cg, int M, int N, int K)
{
    int b = blockIdx.z;
    const float* B = Bg + (size_t)b * K * N;
    float*       C = Cg + (size_t)b * M * N;

    __shared__ float As[16][132];
    __shared__ float Bs[16][132];

    int m0 = blockIdx.y * 128, n0 = blockIdx.x * 128;
    int t = threadIdx.x, tx = t & 15, ty = t >> 4;

    float acc[8][8] = {};

    for (int k0 = 0; k0 < K; k0 += 16) {
        // A tile 128x16 (row-major) -> As[k][m]
        #pragma unroll
        for (int i = 0; i < 2; i++) {
            int idx = t + i * 256;
            int row = idx >> 2, c4 = (idx & 3) * 4;
            float4 v = *(const float4*)&A[(size_t)(m0 + row) * K + k0 + c4];
            As[c4 + 0][row] = v.x; As[c4 + 1][row] = v.y;
            As[c4 + 2][row] = v.z; As[c4 + 3][row] = v.w;
        }
        // B tile 16x128 -> Bs[k][n], optional mean-var normalization per k-row
        #pragma unroll
        for (int i = 0; i < 2; i++) {
            int idx = t + i * 256;
            int kr = idx >> 5, c4 = (idx & 31) * 4;
            float4 v = *(const float4*)&B[(size_t)(k0 + kr) * N + n0 + c4];
            if (NORMB) {
                int si = statOff + b * CHN + k0 + kr;
                float mm = g_mean[si], rr = g_rstd[si];
                v.x = (v.x - mm) * rr; v.y = (v.y - mm) * rr;
                v.z = (v.z - mm) * rr; v.w = (v.w - mm) * rr;
            }
            *(float4*)&Bs[kr][c4] = v;
        }
        __syncthreads();
        MICRO_KERNEL(As, Bs, acc, tx, ty)
        __syncthreads();
    }

    #pragma unroll
    for (int i = 0; i < 8; i++) {
        int m = m0 + ty * 8 + i;
        float bv = bias[m];
        #pragma unroll
        for (int jj = 0; jj < 2; jj++) {
            int n = n0 + tx * 8 + jj * 4;
            float4 o;
            o.x = acc[i][jj * 4 + 0] + bv;
            o.y = acc[i][jj * 4 + 1] + bv;
            o.z = acc[i][jj * 4 + 2] + bv;
            o.w = acc[i][jj * 4 + 3] + bv;
            if (RESID) {
                float4 r = *(const float4*)&residg[(size_t)b * M * N + (size_t)m * N + n];
                o.x += r.x; o.y += r.y; o.z += r.z; o.w += r.w;
            }
            *(float4*)&C[(size_t)m * N + n] = o;
        }
    }
}

// ---------------- GEMM TN: S[b] = F[b]^T (KxM) * G[b] (KxN) -----------------
__global__ void __launch_bounds__(256)
gemm_tn(const float* __restrict__ Ag, const float* __restrict__ Bg,
        float* __restrict__ Cg, int M, int N, int K)
{
    int b = blockIdx.z;
    const float* A = Ag + (size_t)b * K * M;
    const float* B = Bg + (size_t)b * K * N;
    float*       C = Cg + (size_t)b * M * N;

    __shared__ float As[16][132];
    __shared__ float Bs[16][132];

    int m0 = blockIdx.y * 128, n0 = blockIdx.x * 128;
    int t = threadIdx.x, tx = t & 15, ty = t >> 4;

    float acc[8][8] = {};

    for (int k0 = 0; k0 < K; k0 += 16) {
        #pragma unroll
        for (int i = 0; i < 2; i++) {
            int idx = t + i * 256;
            int kr = idx >> 5, c4 = (idx & 31) * 4;
            *(float4*)&As[kr][c4] = *(const float4*)&A[(size_t)(k0 + kr) * M + m0 + c4];
            *(float4*)&Bs[kr][c4] = *(const float4*)&B[(size_t)(k0 + kr) * N + n0 + c4];
        }
        __syncthreads();
        MICRO_KERNEL(As, Bs, acc, tx, ty)
        __syncthreads();
    }

    #pragma unroll
    for (int i = 0; i < 8; i++) {
        int m = m0 + ty * 8 + i;
        #pragma unroll
        for (int jj = 0; jj < 2; jj++) {
            int n = n0 + tx * 8 + jj * 4;
            float4 o;
            o.x = acc[i][jj * 4 + 0]; o.y = acc[i][jj * 4 + 1];
            o.z = acc[i][jj * 4 + 2]; o.w = acc[i][jj * 4 + 3];
            *(float4*)&C[(size_t)m * N + n] = o;
        }
    }
}

// ---------------- GEMM NT: O[b] = H[b] (MxK) * S[b]^T (S is NxK) ------------
__global__ void __launch_bounds__(256)
gemm_nt(const float* __restrict__ Ag, const float* __restrict__ Bg,
        float* __restrict__ Cg, int M, int N, int K)
{
    int b = blockIdx.z;
    const float* A = Ag + (size_t)b * M * K;
    const float* B = Bg + (size_t)b * (size_t)N * K;
    float*       C = Cg + (size_t)b * M * N;

    __shared__ float As[16][132];
    __shared__ float Bs[16][132];

    int m0 = blockIdx.y * 128, n0 = blockIdx.x * 128;
    int t = threadIdx.x, tx = t & 15, ty = t >> 4;

    float acc[8][8] = {};

    for (int k0 = 0; k0 < K; k0 += 16) {
        #pragma unroll
        for (int i = 0; i < 2; i++) {
            int idx = t + i * 256;
            int row = idx >> 2, c4 = (idx & 3) * 4;
            float4 v = *(const float4*)&A[(size_t)(m0 + row) * K + k0 + c4];
            As[c4 + 0][row] = v.x; As[c4 + 1][row] = v.y;
            As[c4 + 2][row] = v.z; As[c4 + 3][row] = v.w;
        }
        #pragma unroll
        for (int i = 0; i < 2; i++) {
            int idx = t + i * 256;
            int row = idx >> 2, c4 = (idx & 3) * 4;     // row = n, c4 = k-chunk
            float4 v = *(const float4*)&B[(size_t)(n0 + row) * K + k0 + c4];
            Bs[c4 + 0][row] = v.x; Bs[c4 + 1][row] = v.y;
            Bs[c4 + 2][row] = v.z; Bs[c4 + 3][row] = v.w;
        }
        __syncthreads();
        MICRO_KERNEL(As, Bs, acc, tx, ty)
        __syncthreads();
    }

    #pragma unroll
    for (int i = 0; i < 8; i++) {
        int m = m0 + ty * 8 + i;
        #pragma unroll
        for (int jj = 0; jj < 2; jj++) {
            int n = n0 + tx * 8 + jj * 4;
            float4 o;
            o.x = acc[i][jj * 4 + 0]; o.y = acc[i][jj * 4 + 1];
            o.z = acc[i][jj * 4 + 2]; o.w = acc[i][jj * 4 + 3];
            *(float4*)&C[(size_t)m * N + n] = o;
        }
    }
}

// ---------------- row softmax over 4096, row cached in smem -----------------
__global__ void __launch_bounds__(256)
softmax_kernel(float* __restrict__ S)
{
    __shared__ float buf[HW];           // 16 KB
    __shared__ float red1[8], red2[8];
    float* p = S + (size_t)blockIdx.x * HW;
    int t = threadIdx.x, lane = t & 31, warp = t >> 5;

    float m = -3.4e38f;
    for (int i = t * 4; i < HW; i += 1024) {
        float4 v = *(const float4*)&p[i];
        *(float4*)&buf[i] = v;
        m = fmaxf(m, fmaxf(fmaxf(v.x, v.y), fmaxf(v.z, v.w)));
    }
    for (int o = 16; o > 0; o >>= 1) m = fmaxf(m, __shfl_xor_sync(0xffffffffu, m, o));
    if (lane == 0) red1[warp] = m;
    __syncthreads();
    if (t < 32) {
        m = (lane < 8) ? red1[lane] : -3.4e38f;
        for (int o = 4; o > 0; o >>= 1) m = fmaxf(m, __shfl_xor_sync(0xffffffffu, m, o));
        if (lane == 0) red1[0] = m;
    }
    __syncthreads();
    m = red1[0];

    float s = 0.f;
    for (int i = t * 4; i < HW; i += 1024) {
        float4 v = *(const float4*)&buf[i];
        v.x = __expf(v.x - m); v.y = __expf(v.y - m);
        v.z = __expf(v.z - m); v.w = __expf(v.w - m);
        *(float4*)&buf[i] = v;
        s += v.x + v.y + v.z + v.w;
    }
    for (int o = 16; o > 0; o >>= 1) s += __shfl_xor_sync(0xffffffffu, s, o);
    if (lane == 0) red2[warp] = s;
    __syncthreads();
    if (t < 32) {
        s = (lane < 8) ? red2[lane] : 0.f;
        for (int o = 4; o > 0; o >>= 1) s += __shfl_xor_sync(0xffffffffu, s, o);
        if (lane == 0) red2[0] = s;
    }
    __syncthreads();
    float inv = 1.0f / red2[0];
    for (int i = t * 4; i < HW; i += 1024) {
        float4 v = *(const float4*)&buf[i];
        v.x *= inv; v.y *= inv; v.z *= inv; v.w *= inv;
        *(float4*)&p[i] = v;
    }
}

// ---------------- launch --------------------------------------------------
extern "C" void kernel_launch(void* const* d_in, const int* in_sizes, int n_in,
                              void* d_out, int out_size)
{
    const float* content = (const float*)d_in[0];
    const float* style   = (const float*)d_in[1];
    const float* Wf = (const float*)d_in[2]; const float* bf = (const float*)d_in[3];
    const float* Wg = (const float*)d_in[4]; const float* bg = (const float*)d_in[5];
    const float* Wh = (const float*)d_in[6]; const float* bh = (const float*)d_in[7];
    const float* Wo = (const float*)d_in[8]; const float* bo = (const float*)d_in[9];
    float* out = (float*)d_out;

    float *pF, *pG, *pH, *pO, *pS;
    cudaGetSymbolAddress((void**)&pF, g_F);
    cudaGetSymbolAddress((void**)&pG, g_G);
    cudaGetSymbolAddress((void**)&pH, g_H);
    cudaGetSymbolAddress((void**)&pO, g_O);
    cudaGetSymbolAddress((void**)&pS, g_S);

    // 1) normalization stats for content & style
    stats_kernel<<<dim3(BATCH * CHN, 2), 256>>>(content, style);

    // 2) F = Wf*norm(content)+bf ; G = Wg*norm(style)+bg ; H = Wh*style+bh
    dim3 gConv(HW / 128, CHN / 128, BATCH);           // (32, 4, 4)
    gemm_nn<true,  false><<<gConv, 256>>>(Wf, content, bf, nullptr, 0,
                                          pF, CHN, HW, CHN);
    gemm_nn<true,  false><<<gConv, 256>>>(Wg, style,   bg, nullptr, BATCH * CHN,
                                          pG, CHN, HW, CHN);
    gemm_nn<false, false><<<gConv, 256>>>(Wh, style,   bh, nullptr, 0,
                                          pH, CHN, HW, CHN);

    // 3) S = F^T G   (per batch 4096x4096, K=512)
    dim3 gS(HW / 128, HW / 128, BATCH);               // (32, 32, 4)
    gemm_tn<<<gS, 256>>>(pF, pG, pS, HW, HW, CHN);

    // 4) softmax rows of S
    softmax_kernel<<<BATCH * HW, 256>>>(pS);

    // 5) O = H * S^T  (per batch 512x4096, K=4096)
    gemm_nt<<<gConv, 256>>>(pH, pS, pO, CHN, HW, HW);

    // 6) out = Wo*O + bo + content
    gemm_nn<false, true><<<gConv, 256>>>(Wo, pO, bo, content, 0,
                                         out, CHN, HW, CHN);
}

// round 3
// speedup vs baseline: 1.2889x; 1.2889x over previous
#include <cuda_runtime.h>
#include <cstdint>
#include <math.h>

#define BATCH 4
#define CHN   512
#define HW    4096
#define EPSF  1e-5f

// ---------------- scratch (device globals; no allocations allowed) ----------
__device__ float g_F[BATCH * CHN * HW];                 // [b][n][c]
__device__ float g_G[BATCH * CHN * HW];                 // [b][n][c]
__device__ float g_H[BATCH * CHN * HW];                 // [b][c][n]
__device__ float g_O[BATCH * CHN * HW];                 // [b][c][n]
__device__ float g_S[(size_t)BATCH * HW * HW];          // [b][n][m]
__device__ float g_mean[2 * BATCH * CHN];
__device__ float g_rstd[2 * BATCH * CHN];

// ============================ helpers =======================================
__device__ __forceinline__ uint32_t smem_to_u32(const void* p) {
    uint32_t a;
    asm("{ .reg .u64 t; cvta.to.shared.u64 t, %1; cvt.u32.u64 %0, t; }"
        : "=r"(a) : "l"(p));
    return a;
}
__device__ __forceinline__ void cp_async16(uint32_t saddr, const void* g) {
    asm volatile("cp.async.ca.shared.global [%0], [%1], 16;"
                 :: "r"(saddr), "l"(g) : "memory");
}
#define CP_COMMIT() asm volatile("cp.async.commit_group;" ::: "memory")
#define CP_WAIT2()  asm volatile("cp.async.wait_group 2;" ::: "memory")

__device__ __forceinline__ void split_tf32(float x, uint32_t& hi, uint32_t& lo) {
    uint32_t h;
    asm("cvt.rna.tf32.f32 %0, %1;" : "=r"(h) : "f"(x));
    float lf = x - __uint_as_float(h);
    uint32_t l;
    asm("cvt.rna.tf32.f32 %0, %1;" : "=r"(l) : "f"(lf));
    hi = h; lo = l;
}

__device__ __forceinline__ void mma_tf32(float* d, const uint32_t* a, const uint32_t* b) {
    asm volatile(
        "mma.sync.aligned.m16n8k8.row.col.f32.tf32.tf32.f32 "
        "{%0,%1,%2,%3}, {%4,%5,%6,%7}, {%8,%9}, {%0,%1,%2,%3};"
        : "+f"(d[0]), "+f"(d[1]), "+f"(d[2]), "+f"(d[3])
        : "r"(a[0]), "r"(a[1]), "r"(a[2]), "r"(a[3]), "r"(b[0]), "r"(b[1]));
}

// =================== mma.sync tf32 3-split GEMM =============================
// D[m,n] = sum_k A[m,k]*B[n,k].  A:[M,K] rm (ld=ldA), B:[N,K] rm (ld=ldB),
// C:[M,N] rm (ld=ldC). K % 32 == 0. 128x128 CTA tile, 8 warps, 3-stage cp.async.
#define TGK_ROWSTRIDE 36
#define TGK_STAGEF    (128 * TGK_ROWSTRIDE)          // floats per stage per mat
#define TGK_SMEMF     (2 * 3 * TGK_STAGEF)           // A(3) + B(3)
#define TGK_SMEMB     (TGK_SMEMF * 4)                // 110592 bytes

__global__ void __launch_bounds__(256, 1)
mma_gemm_kernel(const float* __restrict__ Ag, const float* __restrict__ Bg,
                float* __restrict__ Cg, int K, int ldA, int ldB, int ldC,
                size_t sA, size_t sB, size_t sC)
{
    extern __shared__ float smemf[];
    const uint32_t sb = smem_to_u32(smemf);

    const int t    = threadIdx.x;
    const int lane = t & 31;
    const int wid  = t >> 5;
    const int wm   = wid >> 2;          // 0..1
    const int wn   = wid & 3;           // 0..3
    const int r0   = lane >> 2;         // 0..7
    const int c0   = lane & 3;          // 0..3

    const int b  = blockIdx.z;
    const int m0 = blockIdx.y * 128, n0 = blockIdx.x * 128;
    const float* A = Ag + (size_t)b * sA + (size_t)m0 * ldA;
    const float* B = Bg + (size_t)b * sB + (size_t)n0 * ldB;
    float*       C = Cg + (size_t)b * sC;

    const int NC = K >> 5;

    // ---- async tile loader (stage s <- k-chunk c) ----
    auto load_chunk = [&](int s, int c) {
        const int k0 = c << 5;
        #pragma unroll
        for (int i = 0; i < 4; i++) {
            int idx = t + i * 256;
            int row = idx >> 3, q = idx & 7;
            cp_async16(sb + (uint32_t)(s * TGK_STAGEF + row * TGK_ROWSTRIDE + q * 4) * 4,
                       A + (size_t)row * ldA + k0 + q * 4);
        }
        #pragma unroll
        for (int i = 0; i < 4; i++) {
            int idx = t + i * 256;
            int row = idx >> 3, q = idx & 7;
            cp_async16(sb + (uint32_t)(3 * TGK_STAGEF + s * TGK_STAGEF + row * TGK_ROWSTRIDE + q * 4) * 4,
                       B + (size_t)row * ldB + k0 + q * 4);
        }
        CP_COMMIT();
    };

    float acc[4][4][4] = {};

    int pre = NC < 3 ? NC : 3;
    for (int st = 0; st < pre; st++) load_chunk(st, st);

    for (int c = 0; c < NC; c++) {
        int s = c % 3;
        CP_WAIT2();
        __syncthreads();

        const float* as = smemf + s * TGK_STAGEF;
        const float* bs = smemf + 3 * TGK_STAGEF + s * TGK_STAGEF;

        #pragma unroll
        for (int kk = 0; kk < 4; kk++) {
            uint32_t ah[4][4], al[4][4], bh[4][2], bl[4][2];
            #pragma unroll
            for (int mt = 0; mt < 4; mt++) {
                const float* p = as + (wm * 64 + mt * 16 + r0) * TGK_ROWSTRIDE + kk * 8 + c0;
                split_tf32(p[0],                     ah[mt][0], al[mt][0]);
                split_tf32(p[8 * TGK_ROWSTRIDE],     ah[mt][1], al[mt][1]);
                split_tf32(p[4],                     ah[mt][2], al[mt][2]);
                split_tf32(p[8 * TGK_ROWSTRIDE + 4], ah[mt][3], al[mt][3]);
            }
            #pragma unroll
            for (int nt = 0; nt < 4; nt++) {
                const float* p = bs + (wn * 32 + nt * 8 + r0) * TGK_ROWSTRIDE + kk * 8 + c0;
                split_tf32(p[0], bh[nt][0], bl[nt][0]);
                split_tf32(p[4], bh[nt][1], bl[nt][1]);
            }
            #pragma unroll
            for (int mt = 0; mt < 4; mt++)
                #pragma unroll
                for (int nt = 0; nt < 4; nt++) {
                    mma_tf32(acc[mt][nt], ah[mt], bh[nt]);
                    mma_tf32(acc[mt][nt], ah[mt], bl[nt]);
                    mma_tf32(acc[mt][nt], al[mt], bh[nt]);
                }
        }

        __syncthreads();
        if (c + 3 < NC) load_chunk(s, c + 3);
    }

    // ---- epilogue ----
    #pragma unroll
    for (int mt = 0; mt < 4; mt++) {
        int row = m0 + wm * 64 + mt * 16 + r0;
        #pragma unroll
        for (int nt = 0; nt < 4; nt++) {
            int col = n0 + wn * 32 + nt * 8 + c0 * 2;
            float2 v0 = make_float2(acc[mt][nt][0], acc[mt][nt][1]);
            float2 v1 = make_float2(acc[mt][nt][2], acc[mt][nt][3]);
            *(float2*)&C[(size_t)row * ldC + col]       = v0;
            *(float2*)&C[(size_t)(row + 8) * ldC + col] = v1;
        }
    }
}

// ---------------- per-(b,c) mean / rstd over 4096 spatial elems -------------
__global__ void __launch_bounds__(256)
stats_kernel(const float* __restrict__ content, const float* __restrict__ style)
{
    int bc  = blockIdx.x;
    int sel = blockIdx.y;
    const float* x = (sel == 0 ? content : style) + (size_t)bc * HW;

    float s1 = 0.f, s2 = 0.f;
    for (int i = threadIdx.x * 4; i < HW; i += 256 * 4) {
        float4 v = *(const float4*)&x[i];
        s1 += v.x + v.y + v.z + v.w;
        s2 += v.x * v.x + v.y * v.y + v.z * v.z + v.w * v.w;
    }
    __shared__ float sh1[8], sh2[8];
    for (int o = 16; o > 0; o >>= 1) {
        s1 += __shfl_xor_sync(0xffffffffu, s1, o);
        s2 += __shfl_xor_sync(0xffffffffu, s2, o);
    }
    int warp = threadIdx.x >> 5, lane = threadIdx.x & 31;
    if (lane == 0) { sh1[warp] = s1; sh2[warp] = s2; }
    __syncthreads();
    if (threadIdx.x < 32) {
        s1 = (lane < 8) ? sh1[lane] : 0.f;
        s2 = (lane < 8) ? sh2[lane] : 0.f;
        for (int o = 4; o > 0; o >>= 1) {
            s1 += __shfl_xor_sync(0xffffffffu, s1, o);
            s2 += __shfl_xor_sync(0xffffffffu, s2, o);
        }
        if (lane == 0) {
            float mean = s1 / (float)HW;
            float var  = (s2 - s1 * mean) / (float)(HW - 1);
            int idx = sel * BATCH * CHN + bc;
            g_mean[idx] = mean;
            g_rstd[idx] = rsqrtf(var + EPSF);
        }
    }
}

// ---------------- SIMT conv GEMM (fp32), optional norm/resid/transposed-C ---
#define MICRO_KERNEL(As, Bs, acc, tx, ty)                                      \
    _Pragma("unroll")                                                          \
    for (int kk = 0; kk < 16; kk++) {                                          \
        float ar[8], br[8];                                                    \
        _Pragma("unroll")                                                      \
        for (int i = 0; i < 8; i++) ar[i] = As[kk][(ty) * 8 + i];              \
        _Pragma("unroll")                                                      \
        for (int j = 0; j < 8; j++) br[j] = Bs[kk][(tx) * 8 + j];              \
        _Pragma("unroll")                                                      \
        for (int i = 0; i < 8; i++)                                            \
            _Pragma("unroll")                                                  \
            for (int j = 0; j < 8; j++)                                        \
                acc[i][j] = fmaf(ar[i], br[j], acc[i][j]);                     \
    }

template<bool NORMB, bool RESID, bool TRANSC>
__global__ void __launch_bounds__(256)
gemm_nn(const float* __restrict__ A, const float* __restrict__ Bg,
        const float* __restrict__ bias, const float* __restrict__ residg,
        int statOff, float* __restrict__ Cg, int M, int N, int K)
{
    int b = blockIdx.z;
    const float* B = Bg + (size_t)b * K * N;
    float*       C = Cg + (size_t)b * M * N;

    __shared__ float As[16][132];
    __shared__ float Bs[16][132];

    int m0 = blockIdx.y * 128, n0 = blockIdx.x * 128;
    int t = threadIdx.x, tx = t & 15, ty = t >> 4;

    float acc[8][8] = {};

    for (int k0 = 0; k0 < K; k0 += 16) {
        #pragma unroll
        for (int i = 0; i < 2; i++) {
            int idx = t + i * 256;
            int row = idx >> 2, c4 = (idx & 3) * 4;
            float4 v = *(const float4*)&A[(size_t)(m0 + row) * K + k0 + c4];
            As[c4 + 0][row] = v.x; As[c4 + 1][row] = v.y;
            As[c4 + 2][row] = v.z; As[c4 + 3][row] = v.w;
        }
        #pragma unroll
        for (int i = 0; i < 2; i++) {
            int idx = t + i * 256;
            int kr = idx >> 5, c4 = (idx & 31) * 4;
            float4 v = *(const float4*)&B[(size_t)(k0 + kr) * N + n0 + c4];
            if (NORMB) {
                int si = statOff + b * CHN + k0 + kr;
                float mm = g_mean[si], rr = g_rstd[si];
                v.x = (v.x - mm) * rr; v.y = (v.y - mm) * rr;
                v.z = (v.z - mm) * rr; v.w = (v.w - mm) * rr;
            }
            *(float4*)&Bs[kr][c4] = v;
        }
        __syncthreads();
        MICRO_KERNEL(As, Bs, acc, tx, ty)
        __syncthreads();
    }

    if (TRANSC) {
        float bvs[8];
        #pragma unroll
        for (int i = 0; i < 8; i++) bvs[i] = bias[m0 + ty * 8 + i];
        #pragma unroll
        for (int j = 0; j < 8; j++) {
            int n = n0 + tx * 8 + j;
            float* dst = &C[(size_t)n * M + m0 + ty * 8];
            float4 v0, v1;
            v0.x = acc[0][j] + bvs[0]; v0.y = acc[1][j] + bvs[1];
            v0.z = acc[2][j] + bvs[2]; v0.w = acc[3][j] + bvs[3];
            v1.x = acc[4][j] + bvs[4]; v1.y = acc[5][j] + bvs[5];
            v1.z = acc[6][j] + bvs[6]; v1.w = acc[7][j] + bvs[7];
            *(float4*)dst = v0;
            *(float4*)(dst + 4) = v1;
        }
    } else {
        #pragma unroll
        for (int i = 0; i < 8; i++) {
            int m = m0 + ty * 8 + i;
            float bv = bias[m];
            #pragma unroll
            for (int jj = 0; jj < 2; jj++) {
                int n = n0 + tx * 8 + jj * 4;
                float4 o;
                o.x = acc[i][jj * 4 + 0] + bv;
                o.y = acc[i][jj * 4 + 1] + bv;
                o.z = acc[i][jj * 4 + 2] + bv;
                o.w = acc[i][jj * 4 + 3] + bv;
                if (RESID) {
                    float4 r = *(const float4*)&residg[(size_t)b * M * N + (size_t)m * N + n];
                    o.x += r.x; o.y += r.y; o.z += r.z; o.w += r.w;
                }
                *(float4*)&C[(size_t)m * N + n] = o;
            }
        }
    }
}

// ---------------- row softmax over 4096, row cached in smem -----------------
__global__ void __launch_bounds__(256)
softmax_kernel(float* __restrict__ S)
{
    __shared__ float buf[HW];
    __shared__ float red1[8], red2[8];
    float* p = S + (size_t)blockIdx.x * HW;
    int t = threadIdx.x, lane = t & 31, warp = t >> 5;

    float m = -3.4e38f;
    for (int i = t * 4; i < HW; i += 1024) {
        float4 v = *(const float4*)&p[i];
        *(float4*)&buf[i] = v;
        m = fmaxf(m, fmaxf(fmaxf(v.x, v.y), fmaxf(v.z, v.w)));
    }
    for (int o = 16; o > 0; o >>= 1) m = fmaxf(m, __shfl_xor_sync(0xffffffffu, m, o));
    if (lane == 0) red1[warp] = m;
    __syncthreads();
    if (t < 32) {
        m = (lane < 8) ? red1[lane] : -3.4e38f;
        for (int o = 4; o > 0; o >>= 1) m = fmaxf(m, __shfl_xor_sync(0xffffffffu, m, o));
        if (lane == 0) red1[0] = m;
    }
    __syncthreads();
    m = red1[0];

    float s = 0.f;
    for (int i = t * 4; i < HW; i += 1024) {
        float4 v = *(const float4*)&buf[i];
        v.x = __expf(v.x - m); v.y = __expf(v.y - m);
        v.z = __expf(v.z - m); v.w = __expf(v.w - m);
        *(float4*)&buf[i] = v;
        s += v.x + v.y + v.z + v.w;
    }
    for (int o = 16; o > 0; o >>= 1) s += __shfl_xor_sync(0xffffffffu, s, o);
    if (lane == 0) red2[warp] = s;
    __syncthreads();
    if (t < 32) {
        s = (lane < 8) ? red2[lane] : 0.f;
        for (int o = 4; o > 0; o >>= 1) s += __shfl_xor_sync(0xffffffffu, s, o);
        if (lane == 0) red2[0] = s;
    }
    __syncthreads();
    float inv = 1.0f / red2[0];
    for (int i = t * 4; i < HW; i += 1024) {
        float4 v = *(const float4*)&buf[i];
        v.x *= inv; v.y *= inv; v.z *= inv; v.w *= inv;
        *(float4*)&p[i] = v;
    }
}

// ---------------- launch --------------------------------------------------
extern "C" void kernel_launch(void* const* d_in, const int* in_sizes, int n_in,
                              void* d_out, int out_size)
{
    const float* content = (const float*)d_in[0];
    const float* style   = (const float*)d_in[1];
    const float* Wf = (const float*)d_in[2]; const float* bf = (const float*)d_in[3];
    const float* Wg = (const float*)d_in[4]; const float* bg = (const float*)d_in[5];
    const float* Wh = (const float*)d_in[6]; const float* bh = (const float*)d_in[7];
    const float* Wo = (const float*)d_in[8]; const float* bo = (const float*)d_in[9];
    float* out = (float*)d_out;

    float *pF, *pG, *pH, *pO, *pS;
    cudaGetSymbolAddress((void**)&pF, g_F);
    cudaGetSymbolAddress((void**)&pG, g_G);
    cudaGetSymbolAddress((void**)&pH, g_H);
    cudaGetSymbolAddress((void**)&pO, g_O);
    cudaGetSymbolAddress((void**)&pS, g_S);

    cudaFuncSetAttribute(mma_gemm_kernel,
                         cudaFuncAttributeMaxDynamicSharedMemorySize, TGK_SMEMB);

    // 1) normalization stats
    stats_kernel<<<dim3(BATCH * CHN, 2), 256>>>(content, style);

    // 2) convs: F,G transposed to [n,c]; H normal [c,n]
    dim3 gConv(HW / 128, CHN / 128, BATCH);
    gemm_nn<true,  false, true ><<<gConv, 256>>>(Wf, content, bf, nullptr, 0,
                                                 pF, CHN, HW, CHN);
    gemm_nn<true,  false, true ><<<gConv, 256>>>(Wg, style,   bg, nullptr, BATCH * CHN,
                                                 pG, CHN, HW, CHN);
    gemm_nn<false, false, false><<<gConv, 256>>>(Wh, style,   bh, nullptr, 0,
                                                 pH, CHN, HW, CHN);

    // 3) S[n,m] = sum_c F_t[n,c] * G_t[m,c]   (tensor cores, tf32 3-split)
    mma_gemm_kernel<<<dim3(HW / 128, HW / 128, BATCH), 256, TGK_SMEMB>>>(
        pF, pG, pS, CHN, CHN, CHN, HW,
        (size_t)CHN * HW, (size_t)CHN * HW, (size_t)HW * HW);

    // 4) softmax rows of S
    softmax_kernel<<<BATCH * HW, 256>>>(pS);

    // 5) O[c,n] = sum_m H[c,m] * P[n,m]       (tensor cores, tf32 3-split)
    mma_gemm_kernel<<<dim3(HW / 128, CHN / 128, BATCH), 256, TGK_SMEMB>>>(
        pH, pS, pO, HW, HW, HW, HW,
        (size_t)CHN * HW, (size_t)HW * HW, (size_t)CHN * HW);

    // 6) out = Wo*O + bo + content
    gemm_nn<false, true, false><<<gConv, 256>>>(Wo, pO, bo, content, 0,
                                                out, CHN, HW, CHN);
}

// round 4
// speedup vs baseline: 1.8050x; 1.4004x over previous
#include <cuda_runtime.h>
#include <cstdint>
#include <math.h>

#define BATCH 4
#define CHN   512
#define HW    4096
#define EPSF  1e-5f

// ---------------- scratch (device globals; no allocations allowed) ----------
__device__ float g_F[BATCH * CHN * HW];                 // [b][n][c]
__device__ float g_G[BATCH * CHN * HW];                 // [b][n][c]
__device__ float g_H[BATCH * CHN * HW];                 // [b][c][n]
__device__ float g_O[BATCH * CHN * HW];                 // [b][c][n]
__device__ float g_S[(size_t)BATCH * HW * HW];          // [b][n][m]
__device__ float g_mean[2 * BATCH * CHN];
__device__ float g_rstd[2 * BATCH * CHN];

// ============================ helpers =======================================
__device__ __forceinline__ uint32_t pack_bf16x2(float lo, float hi) {
    uint32_t r;
    asm("cvt.rn.bf16x2.f32 %0, %1, %2;" : "=r"(r) : "f"(hi), "f"(lo));
    return r;
}

__device__ __forceinline__ void mma_bf16(float* d, const uint32_t* a, const uint32_t* b) {
    asm volatile(
        "mma.sync.aligned.m16n8k16.row.col.f32.bf16.bf16.f32 "
        "{%0,%1,%2,%3}, {%4,%5,%6,%7}, {%8,%9}, {%0,%1,%2,%3};"
        : "+f"(d[0]), "+f"(d[1]), "+f"(d[2]), "+f"(d[3])
        : "r"(a[0]), "r"(a[1]), "r"(a[2]), "r"(a[3]), "r"(b[0]), "r"(b[1]));
}

// split one float4 into packed bf16x2 hi/lo pairs (pairs along k)
__device__ __forceinline__ void split4(float4 v, uint32_t& h0, uint32_t& h1,
                                       uint32_t& l0, uint32_t& l1) {
    h0 = pack_bf16x2(v.x, v.y);
    h1 = pack_bf16x2(v.z, v.w);
    float hx = __uint_as_float(h0 << 16);
    float hy = __uint_as_float(h0 & 0xffff0000u);
    float hz = __uint_as_float(h1 << 16);
    float hw = __uint_as_float(h1 & 0xffff0000u);
    l0 = pack_bf16x2(v.x - hx, v.y - hy);
    l1 = pack_bf16x2(v.z - hz, v.w - hw);
}

// =================== bf16 3-split mma GEMM ==================================
// D[m,n] = sum_k A[m,k]*B[n,k]. A:[M,K] rm, B:[N,K] rm, C:[M,N] rm.
// K % 32 == 0. 128x128 CTA tile, 8 warps (2x4), warp tile 64x32.
// smem (u32 units): per stage: Ahi[128][20], Alo, Bhi[128][20], Blo
#define BGK_ROW   20
#define BGK_MAT   (128 * BGK_ROW)                // 2560 u32
#define BGK_STAGE (4 * BGK_MAT)                  // 10240 u32 = 40KB
#define BGK_SMEMB (2 * BGK_STAGE * 4)            // 81920 bytes

__global__ void __launch_bounds__(256, 1)
bf16_gemm_kernel(const float* __restrict__ Ag, const float* __restrict__ Bg,
                 float* __restrict__ Cg, int K, int ldA, int ldB, int ldC,
                 size_t sA, size_t sB, size_t sC)
{
    extern __shared__ uint32_t smem_u32[];

    const int t    = threadIdx.x;
    const int lane = t & 31;
    const int wid  = t >> 5;
    const int wm   = wid >> 2;          // 0..1
    const int wn   = wid & 3;           // 0..3
    const int r0   = lane >> 2;         // 0..7
    const int c0   = lane & 3;          // 0..3

    const int b  = blockIdx.z;
    const int m0 = blockIdx.y * 128, n0 = blockIdx.x * 128;
    const float* A = Ag + (size_t)b * sA + (size_t)m0 * ldA;
    const float* B = Bg + (size_t)b * sB + (size_t)n0 * ldB;
    float*       C = Cg + (size_t)b * sC;

    const int NC = K >> 5;
    const int lrow = t >> 3, lq = t & 7;          // gmem tile mapping

    float4 va[4], vb[4];

    auto gload = [&](int c) {
        const int k0 = c << 5;
        #pragma unroll
        for (int i = 0; i < 4; i++) {
            int row = lrow + i * 32;
            va[i] = *(const float4*)&A[(size_t)row * ldA + k0 + lq * 4];
            vb[i] = *(const float4*)&B[(size_t)row * ldB + k0 + lq * 4];
        }
    };
    auto sstore = [&](int s) {
        uint32_t* base = smem_u32 + s * BGK_STAGE;
        #pragma unroll
        for (int i = 0; i < 4; i++) {
            int row = lrow + i * 32;
            uint32_t off = row * BGK_ROW + lq * 2;
            uint32_t h0, h1, l0, l1;
            split4(va[i], h0, h1, l0, l1);
            base[off] = h0; base[off + 1] = h1;
            base[BGK_MAT + off] = l0; base[BGK_MAT + off + 1] = l1;
            split4(vb[i], h0, h1, l0, l1);
            base[2 * BGK_MAT + off] = h0; base[2 * BGK_MAT + off + 1] = h1;
            base[3 * BGK_MAT + off] = l0; base[3 * BGK_MAT + off + 1] = l1;
        }
    };

    float acc[4][4][4] = {};

    gload(0);
    sstore(0);
    if (NC > 1) gload(1);
    __syncthreads();

    for (int c = 0; c < NC; c++) {
        const int s = c & 1;
        const uint32_t* sa_h = smem_u32 + s * BGK_STAGE;
        const uint32_t* sa_l = sa_h + BGK_MAT;
        const uint32_t* sb_h = sa_h + 2 * BGK_MAT;
        const uint32_t* sb_l = sa_h + 3 * BGK_MAT;

        #pragma unroll
        for (int kk = 0; kk < 2; kk++) {
            uint32_t ah[4][4], al[4][4], bh[4][2], bl[4][2];
            const int cA = kk * 8 + c0;
            #pragma unroll
            for (int mt = 0; mt < 4; mt++) {
                int r = wm * 64 + mt * 16 + r0;
                const uint32_t* ph = &sa_h[r * BGK_ROW + cA];
                const uint32_t* pl = &sa_l[r * BGK_ROW + cA];
                ah[mt][0] = ph[0]; ah[mt][1] = ph[8 * BGK_ROW];
                ah[mt][2] = ph[4]; ah[mt][3] = ph[8 * BGK_ROW + 4];
                al[mt][0] = pl[0]; al[mt][1] = pl[8 * BGK_ROW];
                al[mt][2] = pl[4]; al[mt][3] = pl[8 * BGK_ROW + 4];
            }
            #pragma unroll
            for (int nt = 0; nt < 4; nt++) {
                int n = wn * 32 + nt * 8 + r0;
                bh[nt][0] = sb_h[n * BGK_ROW + cA]; bh[nt][1] = sb_h[n * BGK_ROW + cA + 4];
                bl[nt][0] = sb_l[n * BGK_ROW + cA]; bl[nt][1] = sb_l[n * BGK_ROW + cA + 4];
            }
            #pragma unroll
            for (int mt = 0; mt < 4; mt++)
                #pragma unroll
                for (int nt = 0; nt < 4; nt++) {
                    mma_bf16(acc[mt][nt], ah[mt], bh[nt]);
                    mma_bf16(acc[mt][nt], ah[mt], bl[nt]);
                    mma_bf16(acc[mt][nt], al[mt], bh[nt]);
                }
        }

        __syncthreads();
        if (c + 1 < NC) sstore((c + 1) & 1);
        if (c + 2 < NC) gload(c + 2);
        __syncthreads();
    }

    // ---- epilogue ----
    #pragma unroll
    for (int mt = 0; mt < 4; mt++) {
        int row = m0 + wm * 64 + mt * 16 + r0;
        #pragma unroll
        for (int nt = 0; nt < 4; nt++) {
            int col = n0 + wn * 32 + nt * 8 + c0 * 2;
            *(float2*)&C[(size_t)row * ldC + col] =
                make_float2(acc[mt][nt][0], acc[mt][nt][1]);
            *(float2*)&C[(size_t)(row + 8) * ldC + col] =
                make_float2(acc[mt][nt][2], acc[mt][nt][3]);
        }
    }
}

// ---------------- per-(b,c) mean / rstd over 4096 spatial elems -------------
__global__ void __launch_bounds__(256)
stats_kernel(const float* __restrict__ content, const float* __restrict__ style)
{
    int bc  = blockIdx.x;
    int sel = blockIdx.y;
    const float* x = (sel == 0 ? content : style) + (size_t)bc * HW;

    float s1 = 0.f, s2 = 0.f;
    for (int i = threadIdx.x * 4; i < HW; i += 256 * 4) {
        float4 v = *(const float4*)&x[i];
        s1 += v.x + v.y + v.z + v.w;
        s2 += v.x * v.x + v.y * v.y + v.z * v.z + v.w * v.w;
    }
    __shared__ float sh1[8], sh2[8];
    for (int o = 16; o > 0; o >>= 1) {
        s1 += __shfl_xor_sync(0xffffffffu, s1, o);
        s2 += __shfl_xor_sync(0xffffffffu, s2, o);
    }
    int warp = threadIdx.x >> 5, lane = threadIdx.x & 31;
    if (lane == 0) { sh1[warp] = s1; sh2[warp] = s2; }
    __syncthreads();
    if (threadIdx.x < 32) {
        s1 = (lane < 8) ? sh1[lane] : 0.f;
        s2 = (lane < 8) ? sh2[lane] : 0.f;
        for (int o = 4; o > 0; o >>= 1) {
            s1 += __shfl_xor_sync(0xffffffffu, s1, o);
            s2 += __shfl_xor_sync(0xffffffffu, s2, o);
        }
        if (lane == 0) {
            float mean = s1 / (float)HW;
            float var  = (s2 - s1 * mean) / (float)(HW - 1);
            int idx = sel * BATCH * CHN + bc;
            g_mean[idx] = mean;
            g_rstd[idx] = rsqrtf(var + EPSF);
        }
    }
}

// ---------------- SIMT conv GEMM (fp32), optional norm/resid/transposed-C ---
#define MICRO_KERNEL(As, Bs, acc, tx, ty)                                      \
    _Pragma("unroll")                                                          \
    for (int kk = 0; kk < 16; kk++) {                                          \
        float ar[8], br[8];                                                    \
        _Pragma("unroll")                                                      \
        for (int i = 0; i < 8; i++) ar[i] = As[kk][(ty) * 8 + i];              \
        _Pragma("unroll")                                                      \
        for (int j = 0; j < 8; j++) br[j] = Bs[kk][(tx) * 8 + j];              \
        _Pragma("unroll")                                                      \
        for (int i = 0; i < 8; i++)                                            \
            _Pragma("unroll")                                                  \
            for (int j = 0; j < 8; j++)                                        \
                acc[i][j] = fmaf(ar[i], br[j], acc[i][j]);                     \
    }

template<bool NORMB, bool RESID, bool TRANSC>
__global__ void __launch_bounds__(256)
gemm_nn(const float* __restrict__ A, const float* __restrict__ Bg,
        const float* __restrict__ bias, const float* __restrict__ residg,
        int statOff, float* __restrict__ Cg, int M, int N, int K)
{
    int b = blockIdx.z;
    const float* B = Bg + (size_t)b * K * N;
    float*       C = Cg + (size_t)b * M * N;

    __shared__ float As[16][132];
    __shared__ float Bs[16][132];

    int m0 = blockIdx.y * 128, n0 = blockIdx.x * 128;
    int t = threadIdx.x, tx = t & 15, ty = t >> 4;

    float acc[8][8] = {};

    for (int k0 = 0; k0 < K; k0 += 16) {
        #pragma unroll
        for (int i = 0; i < 2; i++) {
            int idx = t + i * 256;
            int row = idx >> 2, c4 = (idx & 3) * 4;
            float4 v = *(const float4*)&A[(size_t)(m0 + row) * K + k0 + c4];
            As[c4 + 0][row] = v.x; As[c4 + 1][row] = v.y;
            As[c4 + 2][row] = v.z; As[c4 + 3][row] = v.w;
        }
        #pragma unroll
        for (int i = 0; i < 2; i++) {
            int idx = t + i * 256;
            int kr = idx >> 5, c4 = (idx & 31) * 4;
            float4 v = *(const float4*)&B[(size_t)(k0 + kr) * N + n0 + c4];
            if (NORMB) {
                int si = statOff + b * CHN + k0 + kr;
                float mm = g_mean[si], rr = g_rstd[si];
                v.x = (v.x - mm) * rr; v.y = (v.y - mm) * rr;
                v.z = (v.z - mm) * rr; v.w = (v.w - mm) * rr;
            }
            *(float4*)&Bs[kr][c4] = v;
        }
        __syncthreads();
        MICRO_KERNEL(As, Bs, acc, tx, ty)
        __syncthreads();
    }

    if (TRANSC) {
        float bvs[8];
        #pragma unroll
        for (int i = 0; i < 8; i++) bvs[i] = bias[m0 + ty * 8 + i];
        #pragma unroll
        for (int j = 0; j < 8; j++) {
            int n = n0 + tx * 8 + j;
            float* dst = &C[(size_t)n * M + m0 + ty * 8];
            float4 v0, v1;
            v0.x = acc[0][j] + bvs[0]; v0.y = acc[1][j] + bvs[1];
            v0.z = acc[2][j] + bvs[2]; v0.w = acc[3][j] + bvs[3];
            v1.x = acc[4][j] + bvs[4]; v1.y = acc[5][j] + bvs[5];
            v1.z = acc[6][j] + bvs[6]; v1.w = acc[7][j] + bvs[7];
            *(float4*)dst = v0;
            *(float4*)(dst + 4) = v1;
        }
    } else {
        #pragma unroll
        for (int i = 0; i < 8; i++) {
            int m = m0 + ty * 8 + i;
            float bv = bias[m];
            #pragma unroll
            for (int jj = 0; jj < 2; jj++) {
                int n = n0 + tx * 8 + jj * 4;
                float4 o;
                o.x = acc[i][jj * 4 + 0] + bv;
                o.y = acc[i][jj * 4 + 1] + bv;
                o.z = acc[i][jj * 4 + 2] + bv;
                o.w = acc[i][jj * 4 + 3] + bv;
                if (RESID) {
                    float4 r = *(const float4*)&residg[(size_t)b * M * N + (size_t)m * N + n];
                    o.x += r.x; o.y += r.y; o.z += r.z; o.w += r.w;
                }
                *(float4*)&C[(size_t)m * N + n] = o;
            }
        }
    }
}

// ---------------- row softmax over 4096, row cached in smem -----------------
__global__ void __launch_bounds__(256)
softmax_kernel(float* __restrict__ S)
{
    __shared__ float buf[HW];
    __shared__ float red1[8], red2[8];
    float* p = S + (size_t)blockIdx.x * HW;
    int t = threadIdx.x, lane = t & 31, warp = t >> 5;

    float m = -3.4e38f;
    for (int i = t * 4; i < HW; i += 1024) {
        float4 v = *(const float4*)&p[i];
        *(float4*)&buf[i] = v;
        m = fmaxf(m, fmaxf(fmaxf(v.x, v.y), fmaxf(v.z, v.w)));
    }
    for (int o = 16; o > 0; o >>= 1) m = fmaxf(m, __shfl_xor_sync(0xffffffffu, m, o));
    if (lane == 0) red1[warp] = m;
    __syncthreads();
    if (t < 32) {
        m = (lane < 8) ? red1[lane] : -3.4e38f;
        for (int o = 4; o > 0; o >>= 1) m = fmaxf(m, __shfl_xor_sync(0xffffffffu, m, o));
        if (lane == 0) red1[0] = m;
    }
    __syncthreads();
    m = red1[0];

    float s = 0.f;
    for (int i = t * 4; i < HW; i += 1024) {
        float4 v = *(const float4*)&buf[i];
        v.x = __expf(v.x - m); v.y = __expf(v.y - m);
        v.z = __expf(v.z - m); v.w = __expf(v.w - m);
        *(float4*)&buf[i] = v;
        s += v.x + v.y + v.z + v.w;
    }
    for (int o = 16; o > 0; o >>= 1) s += __shfl_xor_sync(0xffffffffu, s, o);
    if (lane == 0) red2[warp] = s;
    __syncthreads();
    if (t < 32) {
        s = (lane < 8) ? red2[lane] : 0.f;
        for (int o = 4; o > 0; o >>= 1) s += __shfl_xor_sync(0xffffffffu, s, o);
        if (lane == 0) red2[0] = s;
    }
    __syncthreads();
    float inv = 1.0f / red2[0];
    for (int i = t * 4; i < HW; i += 1024) {
        float4 v = *(const float4*)&buf[i];
        v.x *= inv; v.y *= inv; v.z *= inv; v.w *= inv;
        *(float4*)&p[i] = v;
    }
}

// ---------------- launch --------------------------------------------------
extern "C" void kernel_launch(void* const* d_in, const int* in_sizes, int n_in,
                              void* d_out, int out_size)
{
    const float* content = (const float*)d_in[0];
    const float* style   = (const float*)d_in[1];
    const float* Wf = (const float*)d_in[2]; const float* bf = (const float*)d_in[3];
    const float* Wg = (const float*)d_in[4]; const float* bg = (const float*)d_in[5];
    const float* Wh = (const float*)d_in[6]; const float* bh = (const float*)d_in[7];
    const float* Wo = (const float*)d_in[8]; const float* bo = (const float*)d_in[9];
    float* out = (float*)d_out;

    float *pF, *pG, *pH, *pO, *pS;
    cudaGetSymbolAddress((void**)&pF, g_F);
    cudaGetSymbolAddress((void**)&pG, g_G);
    cudaGetSymbolAddress((void**)&pH, g_H);
    cudaGetSymbolAddress((void**)&pO, g_O);
    cudaGetSymbolAddress((void**)&pS, g_S);

    cudaFuncSetAttribute(bf16_gemm_kernel,
                         cudaFuncAttributeMaxDynamicSharedMemorySize, BGK_SMEMB);

    // 1) normalization stats
    stats_kernel<<<dim3(BATCH * CHN, 2), 256>>>(content, style);

    // 2) convs: F,G transposed to [n,c]; H normal [c,n]
    dim3 gConv(HW / 128, CHN / 128, BATCH);
    gemm_nn<true,  false, true ><<<gConv, 256>>>(Wf, content, bf, nullptr, 0,
                                                 pF, CHN, HW, CHN);
    gemm_nn<true,  false, true ><<<gConv, 256>>>(Wg, style,   bg, nullptr, BATCH * CHN,
                                                 pG, CHN, HW, CHN);
    gemm_nn<false, false, false><<<gConv, 256>>>(Wh, style,   bh, nullptr, 0,
                                                 pH, CHN, HW, CHN);

    // 3) S[n,m] = sum_c F_t[n,c] * G_t[m,c]   (bf16 3-split tensor cores)
    bf16_gemm_kernel<<<dim3(HW / 128, HW / 128, BATCH), 256, BGK_SMEMB>>>(
        pF, pG, pS, CHN, CHN, CHN, HW,
        (size_t)CHN * HW, (size_t)CHN * HW, (size_t)HW * HW);

    // 4) softmax rows of S
    softmax_kernel<<<BATCH * HW, 256>>>(pS);

    // 5) O[c,n] = sum_m H[c,m] * P[n,m]       (bf16 3-split tensor cores)
    bf16_gemm_kernel<<<dim3(HW / 128, CHN / 128, BATCH), 256, BGK_SMEMB>>>(
        pH, pS, pO, HW, HW, HW, HW,
        (size_t)CHN * HW, (size_t)HW * HW, (size_t)CHN * HW);

    // 6) out = Wo*O + bo + content
    gemm_nn<false, true, false><<<gConv, 256>>>(Wo, pO, bo, content, 0,
                                                out, CHN, HW, CHN);
}

// round 5
// speedup vs baseline: 2.2398x; 1.2409x over previous
#include <cuda_runtime.h>
#include <cstdint>
#include <math.h>

#define BATCH 4
#define CHN   512
#define HW    4096
#define EPSF  1e-5f

// ---------------- scratch (device globals; no allocations allowed) ----------
__device__ float g_CNt[BATCH * CHN * HW];               // norm(content)^T [b][n][c]
__device__ float g_SNt[BATCH * CHN * HW];               // norm(style)^T   [b][n][c]
__device__ float g_St [BATCH * CHN * HW];               // style^T         [b][n][c]
__device__ float g_F[BATCH * CHN * HW];                 // F_t [b][n][c]
__device__ float g_G[BATCH * CHN * HW];                 // G_t [b][n][c]
__device__ float g_H[BATCH * CHN * HW];                 // H   [b][c][n]
__device__ float g_O[BATCH * CHN * HW];                 // O_t [b][n][c]
__device__ float g_S[(size_t)BATCH * HW * HW];          // S   [b][n][m]
__device__ float g_mean[2 * BATCH * CHN];
__device__ float g_rstd[2 * BATCH * CHN];

// ============================ helpers =======================================
__device__ __forceinline__ uint32_t pack_bf16x2(float lo, float hi) {
    uint32_t r;
    asm("cvt.rn.bf16x2.f32 %0, %1, %2;" : "=r"(r) : "f"(hi), "f"(lo));
    return r;
}

__device__ __forceinline__ void mma_bf16(float* d, const uint32_t* a, const uint32_t* b) {
    asm volatile(
        "mma.sync.aligned.m16n8k16.row.col.f32.bf16.bf16.f32 "
        "{%0,%1,%2,%3}, {%4,%5,%6,%7}, {%8,%9}, {%0,%1,%2,%3};"
        : "+f"(d[0]), "+f"(d[1]), "+f"(d[2]), "+f"(d[3])
        : "r"(a[0]), "r"(a[1]), "r"(a[2]), "r"(a[3]), "r"(b[0]), "r"(b[1]));
}

// split one float4 into packed bf16x2 hi/lo pairs (pairs along k)
__device__ __forceinline__ void split4(float4 v, uint32_t& h0, uint32_t& h1,
                                       uint32_t& l0, uint32_t& l1) {
    h0 = pack_bf16x2(v.x, v.y);
    h1 = pack_bf16x2(v.z, v.w);
    float hx = __uint_as_float(h0 << 16);
    float hy = __uint_as_float(h0 & 0xffff0000u);
    float hz = __uint_as_float(h1 << 16);
    float hw = __uint_as_float(h1 & 0xffff0000u);
    l0 = pack_bf16x2(v.x - hx, v.y - hy);
    l1 = pack_bf16x2(v.z - hz, v.w - hw);
}

// =================== bf16 3-split mma GEMM (NT) =============================
// D[m,n] = sum_k A[m,k]*B[n,k]. A:[M,K] rm, B:[N,K] rm, C:[M,N] rm.
// K % 32 == 0. 128x128 CTA tile, 8 warps (2x4), warp tile 64x32.
// BIASMODE: 0=none, 1=bias[m] (per row), 2=bias[n] (per col)
#define BGK_ROW   20
#define BGK_MAT   (128 * BGK_ROW)
#define BGK_STAGE (4 * BGK_MAT)
#define BGK_SMEMB (2 * BGK_STAGE * 4)            // 81920 bytes

template<int BIASMODE, bool RESID>
__global__ void __launch_bounds__(256, 1)
bf16_gemm_kernel(const float* __restrict__ Ag, const float* __restrict__ Bg,
                 const float* __restrict__ bias, const float* __restrict__ residg,
                 float* __restrict__ Cg, int K, int ldA, int ldB, int ldC,
                 size_t sA, size_t sB, size_t sC)
{
    extern __shared__ uint32_t smem_u32[];

    const int t    = threadIdx.x;
    const int lane = t & 31;
    const int wid  = t >> 5;
    const int wm   = wid >> 2;
    const int wn   = wid & 3;
    const int r0   = lane >> 2;
    const int c0   = lane & 3;

    const int b  = blockIdx.z;
    const int m0 = blockIdx.y * 128, n0 = blockIdx.x * 128;
    const float* A = Ag + (size_t)b * sA + (size_t)m0 * ldA;
    const float* B = Bg + (size_t)b * sB + (size_t)n0 * ldB;
    float*       C = Cg + (size_t)b * sC;

    const int NC = K >> 5;
    const int lrow = t >> 3, lq = t & 7;

    float4 va[4], vb[4];

    auto gload = [&](int c) {
        const int k0 = c << 5;
        #pragma unroll
        for (int i = 0; i < 4; i++) {
            int row = lrow + i * 32;
            va[i] = *(const float4*)&A[(size_t)row * ldA + k0 + lq * 4];
            vb[i] = *(const float4*)&B[(size_t)row * ldB + k0 + lq * 4];
        }
    };
    auto sstore = [&](int s) {
        uint32_t* base = smem_u32 + s * BGK_STAGE;
        #pragma unroll
        for (int i = 0; i < 4; i++) {
            int row = lrow + i * 32;
            uint32_t off = row * BGK_ROW + lq * 2;
            uint32_t h0, h1, l0, l1;
            split4(va[i], h0, h1, l0, l1);
            base[off] = h0; base[off + 1] = h1;
            base[BGK_MAT + off] = l0; base[BGK_MAT + off + 1] = l1;
            split4(vb[i], h0, h1, l0, l1);
            base[2 * BGK_MAT + off] = h0; base[2 * BGK_MAT + off + 1] = h1;
            base[3 * BGK_MAT + off] = l0; base[3 * BGK_MAT + off + 1] = l1;
        }
    };

    float acc[4][4][4] = {};

    gload(0);
    sstore(0);
    if (NC > 1) gload(1);
    __syncthreads();

    for (int c = 0; c < NC; c++) {
        const int s = c & 1;
        const uint32_t* sa_h = smem_u32 + s * BGK_STAGE;
        const uint32_t* sa_l = sa_h + BGK_MAT;
        const uint32_t* sb_h = sa_h + 2 * BGK_MAT;
        const uint32_t* sb_l = sa_h + 3 * BGK_MAT;

        #pragma unroll
        for (int kk = 0; kk < 2; kk++) {
            uint32_t ah[4][4], al[4][4], bh[4][2], bl[4][2];
            const int cA = kk * 8 + c0;
            #pragma unroll
            for (int mt = 0; mt < 4; mt++) {
                int r = wm * 64 + mt * 16 + r0;
                const uint32_t* ph = &sa_h[r * BGK_ROW + cA];
                const uint32_t* pl = &sa_l[r * BGK_ROW + cA];
                ah[mt][0] = ph[0]; ah[mt][1] = ph[8 * BGK_ROW];
                ah[mt][2] = ph[4]; ah[mt][3] = ph[8 * BGK_ROW + 4];
                al[mt][0] = pl[0]; al[mt][1] = pl[8 * BGK_ROW];
                al[mt][2] = pl[4]; al[mt][3] = pl[8 * BGK_ROW + 4];
            }
            #pragma unroll
            for (int nt = 0; nt < 4; nt++) {
                int n = wn * 32 + nt * 8 + r0;
                bh[nt][0] = sb_h[n * BGK_ROW + cA]; bh[nt][1] = sb_h[n * BGK_ROW + cA + 4];
                bl[nt][0] = sb_l[n * BGK_ROW + cA]; bl[nt][1] = sb_l[n * BGK_ROW + cA + 4];
            }
            #pragma unroll
            for (int mt = 0; mt < 4; mt++)
                #pragma unroll
                for (int nt = 0; nt < 4; nt++) {
                    mma_bf16(acc[mt][nt], ah[mt], bh[nt]);
                    mma_bf16(acc[mt][nt], ah[mt], bl[nt]);
                    mma_bf16(acc[mt][nt], al[mt], bh[nt]);
                }
        }

        __syncthreads();
        if (c + 1 < NC) sstore((c + 1) & 1);
        if (c + 2 < NC) gload(c + 2);
        __syncthreads();
    }

    // ---- epilogue ----
    #pragma unroll
    for (int mt = 0; mt < 4; mt++) {
        int row = m0 + wm * 64 + mt * 16 + r0;
        float brow0 = 0.f, brow1 = 0.f;
        if (BIASMODE == 1) { brow0 = bias[row]; brow1 = bias[row + 8]; }
        #pragma unroll
        for (int nt = 0; nt < 4; nt++) {
            int col = n0 + wn * 32 + nt * 8 + c0 * 2;
            float2 v0 = make_float2(acc[mt][nt][0], acc[mt][nt][1]);
            float2 v1 = make_float2(acc[mt][nt][2], acc[mt][nt][3]);
            if (BIASMODE == 1) {
                v0.x += brow0; v0.y += brow0;
                v1.x += brow1; v1.y += brow1;
            } else if (BIASMODE == 2) {
                float bx = bias[col], by = bias[col + 1];
                v0.x += bx; v0.y += by;
                v1.x += bx; v1.y += by;
            }
            if (RESID) {
                float2 r0v = *(const float2*)&residg[(size_t)b * sC + (size_t)row * ldC + col];
                float2 r1v = *(const float2*)&residg[(size_t)b * sC + (size_t)(row + 8) * ldC + col];
                v0.x += r0v.x; v0.y += r0v.y;
                v1.x += r1v.x; v1.y += r1v.y;
            }
            *(float2*)&C[(size_t)row * ldC + col]       = v0;
            *(float2*)&C[(size_t)(row + 8) * ldC + col] = v1;
        }
    }
}

// ---------------- per-(b,c) mean / rstd over 4096 spatial elems -------------
__global__ void __launch_bounds__(256)
stats_kernel(const float* __restrict__ content, const float* __restrict__ style)
{
    int bc  = blockIdx.x;
    int sel = blockIdx.y;
    const float* x = (sel == 0 ? content : style) + (size_t)bc * HW;

    float s1 = 0.f, s2 = 0.f;
    for (int i = threadIdx.x * 4; i < HW; i += 256 * 4) {
        float4 v = *(const float4*)&x[i];
        s1 += v.x + v.y + v.z + v.w;
        s2 += v.x * v.x + v.y * v.y + v.z * v.z + v.w * v.w;
    }
    __shared__ float sh1[8], sh2[8];
    for (int o = 16; o > 0; o >>= 1) {
        s1 += __shfl_xor_sync(0xffffffffu, s1, o);
        s2 += __shfl_xor_sync(0xffffffffu, s2, o);
    }
    int warp = threadIdx.x >> 5, lane = threadIdx.x & 31;
    if (lane == 0) { sh1[warp] = s1; sh2[warp] = s2; }
    __syncthreads();
    if (threadIdx.x < 32) {
        s1 = (lane < 8) ? sh1[lane] : 0.f;
        s2 = (lane < 8) ? sh2[lane] : 0.f;
        for (int o = 4; o > 0; o >>= 1) {
            s1 += __shfl_xor_sync(0xffffffffu, s1, o);
            s2 += __shfl_xor_sync(0xffffffffu, s2, o);
        }
        if (lane == 0) {
            float mean = s1 / (float)HW;
            float var  = (s2 - s1 * mean) / (float)(HW - 1);
            int idx = sel * BATCH * CHN + bc;
            g_mean[idx] = mean;
            g_rstd[idx] = rsqrtf(var + EPSF);
        }
    }
}

// ------- transpose + normalize: [b][c][n] -> [b][n][c], 3 outputs ----------
__global__ void __launch_bounds__(256)
transnorm_kernel(const float* __restrict__ content, const float* __restrict__ style,
                 float* __restrict__ CNt, float* __restrict__ SNt,
                 float* __restrict__ St)
{
    __shared__ float tc[32][33], ts[32][33];
    int b  = blockIdx.z;
    int c0 = blockIdx.y * 32, n0 = blockIdx.x * 32;
    int t  = threadIdx.x;
    int r  = t >> 3, q = (t & 7) * 4;

    size_t ib = (size_t)b * CHN * HW + (size_t)(c0 + r) * HW + n0 + q;
    // content: normalize at load (per channel row)
    float mC = g_mean[b * CHN + c0 + r], rC = g_rstd[b * CHN + c0 + r];
    float4 v = *(const float4*)&content[ib];
    tc[r][q + 0] = (v.x - mC) * rC; tc[r][q + 1] = (v.y - mC) * rC;
    tc[r][q + 2] = (v.z - mC) * rC; tc[r][q + 3] = (v.w - mC) * rC;
    float4 w = *(const float4*)&style[ib];
    ts[r][q + 0] = w.x; ts[r][q + 1] = w.y; ts[r][q + 2] = w.z; ts[r][q + 3] = w.w;
    __syncthreads();

    // write: n = n0 + r along rows, c = c0 + q..q+3 contiguous
    size_t ob = (size_t)b * CHN * HW + (size_t)(n0 + r) * CHN + c0 + q;
    float4 o;
    o.x = tc[q + 0][r]; o.y = tc[q + 1][r]; o.z = tc[q + 2][r]; o.w = tc[q + 3][r];
    *(float4*)&CNt[ob] = o;

    float4 sraw;
    sraw.x = ts[q + 0][r]; sraw.y = ts[q + 1][r];
    sraw.z = ts[q + 2][r]; sraw.w = ts[q + 3][r];
    *(float4*)&St[ob] = sraw;

    int sidx = BATCH * CHN + b * CHN + c0 + q;
    float4 sm = *(const float4*)&g_mean[sidx];
    float4 sr = *(const float4*)&g_rstd[sidx];
    float4 sn;
    sn.x = (sraw.x - sm.x) * sr.x; sn.y = (sraw.y - sm.y) * sr.y;
    sn.z = (sraw.z - sm.z) * sr.z; sn.w = (sraw.w - sm.w) * sr.w;
    *(float4*)&SNt[ob] = sn;
}

// ---------------- row softmax over 4096, row cached in smem -----------------
__global__ void __launch_bounds__(256)
softmax_kernel(float* __restrict__ S)
{
    __shared__ float buf[HW];
    __shared__ float red1[8], red2[8];
    float* p = S + (size_t)blockIdx.x * HW;
    int t = threadIdx.x, lane = t & 31, warp = t >> 5;

    float m = -3.4e38f;
    for (int i = t * 4; i < HW; i += 1024) {
        float4 v = *(const float4*)&p[i];
        *(float4*)&buf[i] = v;
        m = fmaxf(m, fmaxf(fmaxf(v.x, v.y), fmaxf(v.z, v.w)));
    }
    for (int o = 16; o > 0; o >>= 1) m = fmaxf(m, __shfl_xor_sync(0xffffffffu, m, o));
    if (lane == 0) red1[warp] = m;
    __syncthreads();
    if (t < 32) {
        m = (lane < 8) ? red1[lane] : -3.4e38f;
        for (int o = 4; o > 0; o >>= 1) m = fmaxf(m, __shfl_xor_sync(0xffffffffu, m, o));
        if (lane == 0) red1[0] = m;
    }
    __syncthreads();
    m = red1[0];

    float s = 0.f;
    for (int i = t * 4; i < HW; i += 1024) {
        float4 v = *(const float4*)&buf[i];
        v.x = __expf(v.x - m); v.y = __expf(v.y - m);
        v.z = __expf(v.z - m); v.w = __expf(v.w - m);
        *(float4*)&buf[i] = v;
        s += v.x + v.y + v.z + v.w;
    }
    for (int o = 16; o > 0; o >>= 1) s += __shfl_xor_sync(0xffffffffu, s, o);
    if (lane == 0) red2[warp] = s;
    __syncthreads();
    if (t < 32) {
        s = (lane < 8) ? red2[lane] : 0.f;
        for (int o = 4; o > 0; o >>= 1) s += __shfl_xor_sync(0xffffffffu, s, o);
        if (lane == 0) red2[0] = s;
    }
    __syncthreads();
    float inv = 1.0f / red2[0];
    for (int i = t * 4; i < HW; i += 1024) {
        float4 v = *(const float4*)&buf[i];
        v.x *= inv; v.y *= inv; v.z *= inv; v.w *= inv;
        *(float4*)&p[i] = v;
    }
}

// ---------------- launch --------------------------------------------------
extern "C" void kernel_launch(void* const* d_in, const int* in_sizes, int n_in,
                              void* d_out, int out_size)
{
    const float* content = (const float*)d_in[0];
    const float* style   = (const float*)d_in[1];
    const float* Wf = (const float*)d_in[2]; const float* bf = (const float*)d_in[3];
    const float* Wg = (const float*)d_in[4]; const float* bg = (const float*)d_in[5];
    const float* Wh = (const float*)d_in[6]; const float* bh = (const float*)d_in[7];
    const float* Wo = (const float*)d_in[8]; const float* bo = (const float*)d_in[9];
    float* out = (float*)d_out;

    float *pCNt, *pSNt, *pSt, *pF, *pG, *pH, *pO, *pS;
    cudaGetSymbolAddress((void**)&pCNt, g_CNt);
    cudaGetSymbolAddress((void**)&pSNt, g_SNt);
    cudaGetSymbolAddress((void**)&pSt,  g_St);
    cudaGetSymbolAddress((void**)&pF, g_F);
    cudaGetSymbolAddress((void**)&pG, g_G);
    cudaGetSymbolAddress((void**)&pH, g_H);
    cudaGetSymbolAddress((void**)&pO, g_O);
    cudaGetSymbolAddress((void**)&pS, g_S);

    cudaFuncSetAttribute(bf16_gemm_kernel<0, false>,
                         cudaFuncAttributeMaxDynamicSharedMemorySize, BGK_SMEMB);
    cudaFuncSetAttribute(bf16_gemm_kernel<1, false>,
                         cudaFuncAttributeMaxDynamicSharedMemorySize, BGK_SMEMB);
    cudaFuncSetAttribute(bf16_gemm_kernel<2, false>,
                         cudaFuncAttributeMaxDynamicSharedMemorySize, BGK_SMEMB);
    cudaFuncSetAttribute(bf16_gemm_kernel<1, true>,
                         cudaFuncAttributeMaxDynamicSharedMemorySize, BGK_SMEMB);

    const size_t sBCHW = (size_t)CHN * HW;

    // 1) normalization stats
    stats_kernel<<<dim3(BATCH * CHN, 2), 256>>>(content, style);

    // 2) transpose + normalize: CN_t, SN_t, St  ([b][n][c])
    transnorm_kernel<<<dim3(HW / 32, CHN / 32, BATCH), 256>>>(
        content, style, pCNt, pSNt, pSt);

    // 3) F_t[n,c] = CN_t[n,:] . Wf[c,:]   (bias per col)
    bf16_gemm_kernel<2, false><<<dim3(CHN / 128, HW / 128, BATCH), 256, BGK_SMEMB>>>(
        pCNt, Wf, bf, nullptr, pF, CHN, CHN, CHN, CHN, sBCHW, 0, sBCHW);

    // 4) G_t[n,c] = SN_t[n,:] . Wg[c,:]   (bias per col)
    bf16_gemm_kernel<2, false><<<dim3(CHN / 128, HW / 128, BATCH), 256, BGK_SMEMB>>>(
        pSNt, Wg, bg, nullptr, pG, CHN, CHN, CHN, CHN, sBCHW, 0, sBCHW);

    // 5) H[c,n] = Wh[c,:] . St[n,:]       (bias per row)
    bf16_gemm_kernel<1, false><<<dim3(HW / 128, CHN / 128, BATCH), 256, BGK_SMEMB>>>(
        Wh, pSt, bh, nullptr, pH, CHN, CHN, CHN, HW, 0, sBCHW, sBCHW);

    // 6) S[n,m] = F_t[n,:] . G_t[m,:]
    bf16_gemm_kernel<0, false><<<dim3(HW / 128, HW / 128, BATCH), 256, BGK_SMEMB>>>(
        pF, pG, nullptr, nullptr, pS, CHN, CHN, CHN, HW,
        sBCHW, sBCHW, (size_t)HW * HW);

    // 7) softmax rows of S
    softmax_kernel<<<BATCH * HW, 256>>>(pS);

    // 8) O_t[n,c] = P[n,:] . H[c,:]       (K = HW)
    bf16_gemm_kernel<0, false><<<dim3(CHN / 128, HW / 128, BATCH), 256, BGK_SMEMB>>>(
        pS, pH, nullptr, nullptr, pO, HW, HW, HW, CHN,
        (size_t)HW * HW, sBCHW, sBCHW);

    // 9) out[c,n] = Wo[c,:] . O_t[n,:] + bo + content   (bias per row + resid)
    bf16_gemm_kernel<1, true><<<dim3(HW / 128, CHN / 128, BATCH), 256, BGK_SMEMB>>>(
        Wo, pO, bo, content, out, CHN, CHN, CHN, HW, 0, sBCHW, sBCHW);
}